// round 4
// baseline (speedup 1.0000x reference)
#include <cuda_runtime.h>
#include <cstddef>
#include <cstdint>

// ErbNorm: per-(b,f) EMA normalization scan over T.
//   mu_t  = a*mu_{t-1} + (1-a)*x_t
//   var_t = a*var_{t-1} + (1-a)*(x_t - mu_t)^2
//   out_t = (x_t - mu_t) / (sqrt(var_t) + eps)
//
// Round 4: the kernel was per-warp issue-bound at 0.86 warps/SMSP. Split T
// into 2 chunks per (b, f-half) lane group -> 1024 warps (1.73/SMSP) so
// co-resident warps hide each other's stalls. Chunk 1 starts from an
// approximate state (mu=0, var=1) and burns in 1024 read-only steps; the EMA
// contracts errors by 0.99^1024 ~ 3e-5, far under the 1e-3 tolerance.
// Chunk lengths (2240 / 1760+1024 burn) balance per-warp issue work.
// Data path unchanged from round 3: cp.async smem ring (8 slots x 16 steps x
// 128B) + register double-buffer, even/odd-unrolled bodies.

#ifndef ERB_T
#define ERB_T 4000
#endif
#define ERB_F   64
#define ERB_G   16                   // timesteps per commit group
#define ERB_NGR 8                    // ring slots
#define ERB_SLOT_FLOATS (ERB_G * 32)
#define ERB_SLOT_BYTES  (ERB_G * 128)

#define ERB_L0      2240             // chunk-0 scan length (multiple of 32)
#define ERB_WBURN   1024             // chunk-1 burn-in steps (multiple of 32)

__device__ __forceinline__ void cp_async16(uint32_t saddr, const void* gaddr) {
    asm volatile("cp.async.cg.shared.global [%0], [%1], 16;\n"
                 :: "r"(saddr), "l"(gaddr));
}
__device__ __forceinline__ void cp_commit() {
    asm volatile("cp.async.commit_group;\n");
}
__device__ __forceinline__ void cp_wait7() {
    asm volatile("cp.async.wait_group 7;\n");
}

__global__ void __launch_bounds__(32)
erbnorm_kernel(const float* __restrict__ x, float* __restrict__ out, int T)
{
    __shared__ float buf[ERB_NGR * ERB_SLOT_FLOATS];   // 16KB

    const int tid   = threadIdx.x;
    const int chunk = blockIdx.x & 1;
    const int half  = (blockIdx.x >> 1) & 1;
    const int b     = blockIdx.x >> 2;
    const int f     = (half << 5) + tid;

    const float alpha = 0.99f;
    const float beta  = (float)(1.0 - 0.99);
    const float kvar  = (float)((1.0 - 0.99) * 0.99 * 0.99);  // beta*alpha^2
    const float step  = (float)((-90.0 - (-60.0)) / 63.0);

    // Chunk-dependent schedule.
    const int t_stream = chunk ? (ERB_L0 - ERB_WBURN) : 0;   // first t loaded
    const int t_scan   = chunk ? ERB_L0 : 0;                  // first t stored
    const int n_steps  = chunk ? (T - ERB_L0 + ERB_WBURN) : ERB_L0;
    const int NG       = n_steps / ERB_G;                     // total groups
    const int nburn    = chunk ? (ERB_WBURN / ERB_G) : 0;     // burn groups

    float mu  = chunk ? 0.0f : fmaf((float)f, step, -60.0f);
    float var = chunk ? 1.0f : 1600.0f;

    const size_t half_base = (size_t)b * (size_t)T * ERB_F + (size_t)(half << 5);

    // Cooperative load mapping: 8 threads cover one 128B stage (4 rows each).
    const int r_off = tid >> 3;
    const int c_off = (tid & 7) * 4;

    const float* gsrc = x + half_base + (size_t)(t_stream + r_off) * ERB_F + c_off;
    const uint32_t sbase =
        (uint32_t)__cvta_generic_to_shared(buf) + (uint32_t)(r_off * 128 + c_off * 4);

    // ---- prologue: fill all 8 slots ----
    {
        const float* p = gsrc;
        uint32_t sa = sbase;
        #pragma unroll
        for (int grp = 0; grp < ERB_NGR; ++grp) {
            #pragma unroll
            for (int r = 0; r < 4; ++r)
                cp_async16(sa + (uint32_t)(r * 4 * 128), p + (size_t)(r * 4) * ERB_F);
            cp_commit();
            sa += ERB_SLOT_BYTES;
            p  += (size_t)ERB_G * ERB_F;
        }
    }

    const float* sp   = &buf[tid];
    float*       q    = out + half_base + (size_t)t_scan * ERB_F + tid;
    const float* pref = gsrc + (size_t)ERB_NGR * ERB_G * ERB_F;

    float A[ERB_G], Bv[ERB_G];

    // Load group 0 into A.
    cp_wait7();
    __syncwarp();
    #pragma unroll
    for (int i = 0; i < ERB_G; ++i) A[i] = sp[i * 32];

    // Shared ring maintenance: refill freed slot, fetch next group into NXT.
#define ERB_RING(NXT, g)                                                       \
    {                                                                          \
        if ((g) + ERB_NGR < NG) {                                              \
            uint32_t sa = sbase + (uint32_t)(((g) & 7) * ERB_SLOT_BYTES);      \
            _Pragma("unroll")                                                  \
            for (int r = 0; r < 4; ++r)                                        \
                cp_async16(sa + (uint32_t)(r * 4 * 128),                       \
                           pref + (size_t)(r * 4) * ERB_F);                    \
            pref += (size_t)ERB_G * ERB_F;                                     \
        }                                                                      \
        cp_commit();                                                           \
        cp_wait7();                                                            \
        __syncwarp();                                                          \
        {                                                                      \
            const float* sn = sp + (((g) + 1) & 7) * ERB_SLOT_FLOATS;          \
            _Pragma("unroll")                                                  \
            for (int i = 0; i < ERB_G; ++i) NXT[i] = sn[i * 32];               \
        }                                                                      \
    }

    // Burn-in: evolve (mu, var) only — no rsqrt, no store.
#define ERB_BURN(CUR, NXT, g)                                                  \
    {                                                                          \
        ERB_RING(NXT, g)                                                       \
        _Pragma("unroll")                                                      \
        for (int i = 0; i < ERB_G; ++i) {                                      \
            float d0 = CUR[i] - mu;                                            \
            mu = fmaf(beta, d0, mu);                                           \
            var = fmaf(alpha, var, (kvar * d0) * d0);                          \
        }                                                                      \
    }

    // Full scan step: d = alpha*d0 equals x - mu_new; out = d*rsqrt(var).
#define ERB_SCAN(CUR, NXT, g)                                                  \
    {                                                                          \
        ERB_RING(NXT, g)                                                       \
        _Pragma("unroll")                                                      \
        for (int i = 0; i < ERB_G; ++i) {                                      \
            float d0 = CUR[i] - mu;                                            \
            mu = fmaf(beta, d0, mu);                                           \
            float d = alpha * d0;                                              \
            var = fmaf(alpha, var, (kvar * d0) * d0);                          \
            __stcs(q + i * ERB_F, d * rsqrtf(var));                            \
        }                                                                      \
        q += ERB_G * ERB_F;                                                    \
    }

    int g = 0;
    for (; g < nburn; g += 2) {        // nburn even (64 or 0)
        ERB_BURN(A, Bv, g)
        ERB_BURN(Bv, A, g + 1)
    }
    for (; g < NG; g += 2) {           // NG - nburn even (140 / 110)
        ERB_SCAN(A, Bv, g)
        ERB_SCAN(Bv, A, g + 1)
    }
#undef ERB_RING
#undef ERB_BURN
#undef ERB_SCAN
}

extern "C" void kernel_launch(void* const* d_in, const int* in_sizes, int n_in,
                              void* d_out, int out_size)
{
    const float* x = (const float*)d_in[0];
    float* out = (float*)d_out;

    const int T = ERB_T;                       // 4000
    const int B = in_sizes[0] / (T * ERB_F);   // 256

    dim3 grid(B * 4);   // (b, half, chunk) -> 1024 single-warp blocks
    dim3 block(32);
    erbnorm_kernel<<<grid, block>>>(x, out, T);
}

// round 5
// speedup vs baseline: 1.1303x; 1.1303x over previous
#include <cuda_runtime.h>
#include <cstddef>
#include <cstdint>

// ErbNorm: per-(b,f) EMA normalization scan over T.
//   mu_t  = a*mu_{t-1} + (1-a)*x_t
//   var_t = a*var_{t-1} + (1-a)*(x_t - mu_t)^2
//   out_t = (x_t - mu_t) / (sqrt(var_t) + eps)
//
// Round 5: chip saturates at ~5.6TB/s (R4 proved occupancy doesn't move it).
// Target the achieved-bandwidth ceiling itself:
//   - one 64-thread CTA per b: both f-halves stream adjacent 128B in lockstep
//     -> contiguous 256B/step per CTA at the memory controller
//   - write batching: 16 output steps staged in smem, then burst as 4 STG.128
//     per thread-group (2KB dense per warp) -> fewer R/W turnarounds
// Data path otherwise round-3: cp.async ring (8 slots x 16 steps x 128B per
// warp) + register double-buffer, even/odd-unrolled bodies.

#ifndef ERB_T
#define ERB_T 4000
#endif
#define ERB_F   64
#define ERB_G   16
#define ERB_NGR 8
#define ERB_SLOT_FLOATS (ERB_G * 32)
#define ERB_SLOT_BYTES  (ERB_G * 128)

__device__ __forceinline__ void cp_async16(uint32_t saddr, const void* gaddr) {
    asm volatile("cp.async.cg.shared.global [%0], [%1], 16;\n"
                 :: "r"(saddr), "l"(gaddr));
}
__device__ __forceinline__ void cp_commit() {
    asm volatile("cp.async.commit_group;\n");
}
__device__ __forceinline__ void cp_wait7() {
    asm volatile("cp.async.wait_group 7;\n");
}

__global__ void __launch_bounds__(64)
erbnorm_kernel(const float* __restrict__ x, float* __restrict__ out, int T)
{
    // Per-warp cp.async ring (16KB each) + per-warp double-buffered store stage.
    __shared__ __align__(128) float buf[2][ERB_NGR * ERB_SLOT_FLOATS];  // 32KB
    __shared__ __align__(128) float obuf[2][2][ERB_G * 32];             // 8KB

    const int tid  = threadIdx.x;     // 0..63
    const int w    = tid >> 5;        // f-half
    const int lane = tid & 31;
    const int b    = blockIdx.x;
    const int f    = (w << 5) + lane;

    const float alpha = 0.99f;
    const float beta  = (float)(1.0 - 0.99);
    const float kvar  = (float)((1.0 - 0.99) * 0.99 * 0.99);   // beta*alpha^2
    const float step  = (float)((-90.0 - (-60.0)) / 63.0);

    float mu  = fmaf((float)f, step, -60.0f);
    float var = 1600.0f;

    // This warp's 128B column base (f-half of batch b).
    const size_t base = (size_t)b * (size_t)T * ERB_F + (size_t)(w << 5);

    // Cooperative mapping: 8 lanes cover one 128B stage row; 4 rows per lane.
    const int r_off = lane >> 3;
    const int c_off = (lane & 7) * 4;

    const float* gsrc = x + base + (size_t)r_off * ERB_F + c_off;
    const uint32_t sbase =
        (uint32_t)__cvta_generic_to_shared(&buf[w][0])
        + (uint32_t)(r_off * 128 + c_off * 4);

    // ---- prologue: fill all 8 ring slots ----
    {
        const float* p = gsrc;
        uint32_t sa = sbase;
        #pragma unroll
        for (int grp = 0; grp < ERB_NGR; ++grp) {
            #pragma unroll
            for (int r = 0; r < 4; ++r)
                cp_async16(sa + (uint32_t)(r * 4 * 128), p + (size_t)(r * 4) * ERB_F);
            cp_commit();
            sa += ERB_SLOT_BYTES;
            p  += (size_t)ERB_G * ERB_F;
        }
    }

    const int NG = T / ERB_G;                   // 250 (even)
    const float* sp   = &buf[w][lane];          // this lane's smem read column
    float*       qrow = out + base;             // warp-level output row base
    const float* pref = gsrc + (size_t)ERB_NGR * ERB_G * ERB_F;

    float A[ERB_G], Bv[ERB_G];

    cp_wait7();
    __syncwarp();
    #pragma unroll
    for (int i = 0; i < ERB_G; ++i) A[i] = sp[i * 32];

    // Ring maintenance: refill freed slot, pull group g+1 into NXT registers.
#define ERB_RING(NXT, g)                                                       \
    {                                                                          \
        if ((g) + ERB_NGR < NG) {                                              \
            uint32_t sa = sbase + (uint32_t)(((g) & 7) * ERB_SLOT_BYTES);      \
            _Pragma("unroll")                                                  \
            for (int r = 0; r < 4; ++r)                                        \
                cp_async16(sa + (uint32_t)(r * 4 * 128),                       \
                           pref + (size_t)(r * 4) * ERB_F);                    \
            pref += (size_t)ERB_G * ERB_F;                                     \
        }                                                                      \
        cp_commit();                                                           \
        cp_wait7();                                                            \
        __syncwarp();                                                          \
        {                                                                      \
            const float* sn = sp + (((g) + 1) & 7) * ERB_SLOT_FLOATS;          \
            _Pragma("unroll")                                                  \
            for (int i = 0; i < ERB_G; ++i) NXT[i] = sn[i * 32];               \
        }                                                                      \
    }

    // Scan group g from CUR into the staging tile, then burst-write 2KB.
    // Staging parity (g&1) double-buffers so one __syncwarp per group suffices
    // (WAR on obuf spans 2 groups and crosses later syncwarps).
#define ERB_SCAN(CUR, NXT, g, P)                                               \
    {                                                                          \
        ERB_RING(NXT, g)                                                       \
        float* ob = &obuf[w][P][0];                                            \
        _Pragma("unroll")                                                      \
        for (int i = 0; i < ERB_G; ++i) {                                      \
            float d0 = CUR[i] - mu;                                            \
            mu = fmaf(beta, d0, mu);                                           \
            float d = alpha * d0;                                              \
            var = fmaf(alpha, var, (kvar * d0) * d0);                          \
            ob[i * 32 + lane] = d * rsqrtf(var);                               \
        }                                                                      \
        __syncwarp();                                                          \
        _Pragma("unroll")                                                      \
        for (int k = 0; k < 4; ++k) {                                          \
            int r = r_off + k * 4;                                             \
            float4 v = *reinterpret_cast<const float4*>(&ob[r * 32 + c_off]);  \
            __stcs(reinterpret_cast<float4*>(qrow + (size_t)r * ERB_F + c_off),\
                   v);                                                         \
        }                                                                      \
        qrow += ERB_G * ERB_F;                                                 \
    }

    for (int g = 0; g < NG; g += 2) {
        ERB_SCAN(A, Bv, g, 0)
        ERB_SCAN(Bv, A, g + 1, 1)
    }
#undef ERB_RING
#undef ERB_SCAN
}

extern "C" void kernel_launch(void* const* d_in, const int* in_sizes, int n_in,
                              void* d_out, int out_size)
{
    const float* x = (const float*)d_in[0];
    float* out = (float*)d_out;

    const int T = ERB_T;                       // 4000
    const int B = in_sizes[0] / (T * ERB_F);   // 256

    dim3 grid(B);       // one 64-thread CTA per batch row
    dim3 block(64);
    erbnorm_kernel<<<grid, block>>>(x, out, T);
}